// round 7
// baseline (speedup 1.0000x reference)
#include <cuda_runtime.h>
#include <math.h>

// Problem constants
#define BATCH     16384
#define NUM_F     32
#define EMBED     64
#define NPAIRS    496          // 32*31/2
#define THREADS   256
#define ROWS_CTA  2

// x: [BATCH, 32, 64] f32  -> viewed as [BATCH, 512] float4
// out: [BATCH, 496] f32   -> row is 1984 bytes = 124 * float4 (16B aligned per row)
__global__ __launch_bounds__(THREADS, 8)
void opn_kernel(const float4* __restrict__ x, float4* __restrict__ out)
{
    const int tid = threadIdx.x;
    const int b0  = blockIdx.x * ROWS_CTA;

    __shared__ float s[ROWS_CTA][NUM_F];

    // ---- load + reduce: field f = tid>>3, 8 threads per field, 8 floats/row ----
    const int f   = tid >> 3;
    const int sub = tid & 7;
    const int gi  = f * 16 + sub * 2;                 // float4 index within a row

    const float4* xb0 = x + (size_t)b0 * (NUM_F * EMBED / 4);   // 512 float4/row
    const float4* xb1 = xb0 + (NUM_F * EMBED / 4);

    // 4 front-batched LDG.128, all perfectly coalesced per instruction
    float4 a0 = xb0[gi];
    float4 a1 = xb0[gi + 1];
    float4 c0 = xb1[gi];
    float4 c1 = xb1[gi + 1];

    float v0 = (a0.x + a0.y) + (a0.z + a0.w) + (a1.x + a1.y) + (a1.z + a1.w);
    float v1 = (c0.x + c0.y) + (c0.z + c0.w) + (c1.x + c1.y) + (c1.z + c1.w);

    // reduce across the 8 lanes of each field (independent chains overlap)
    v0 += __shfl_down_sync(0xffffffffu, v0, 4);
    v1 += __shfl_down_sync(0xffffffffu, v1, 4);
    v0 += __shfl_down_sync(0xffffffffu, v0, 2);
    v1 += __shfl_down_sync(0xffffffffu, v1, 2);
    v0 += __shfl_down_sync(0xffffffffu, v0, 1);
    v1 += __shfl_down_sync(0xffffffffu, v1, 1);
    if (sub == 0) { s[0][f] = v0; s[1][f] = v1; }
    __syncthreads();

    // ---- pairwise products: threads 0..123 -> row0, 128..251 -> row1 ----
    const int r = tid >> 7;          // 0 or 1
    const int t = tid & 127;
    if (t < NPAIRS / 4) {
        int p = t * 4;

        // analytic p -> (i, j): start(i) = i*(63-i)/2, pairs ordered i asc, j asc
        float fi = (63.0f - sqrtf(3969.0f - 8.0f * (float)p)) * 0.5f;
        int i = (int)fi;
        // integer fix-up against float rounding
        int st = (i * (63 - i)) >> 1;
        while (st > p)                         { --i; st = (i * (63 - i)) >> 1; }
        while (((i + 1) * (62 - i)) >> 1 <= p) { ++i; st = (i * (63 - i)) >> 1; }
        int j = i + 1 + (p - st);

        const float* sr = s[r];
        float4 rv;
        float* rp = &rv.x;
        #pragma unroll
        for (int k = 0; k < 4; ++k) {
            rp[k] = sr[i] * sr[j];
            ++j;
            if (j == NUM_F) { ++i; j = i + 1; }
        }
        out[(size_t)(b0 + r) * (NPAIRS / 4) + t] = rv;
    }
}

extern "C" void kernel_launch(void* const* d_in, const int* in_sizes, int n_in,
                              void* d_out, int out_size)
{
    const float4* x   = (const float4*)d_in[0];
    float4*       out = (float4*)d_out;
    opn_kernel<<<BATCH / ROWS_CTA, THREADS>>>(x, out);
}